// round 1
// baseline (speedup 1.0000x reference)
#include <cuda_runtime.h>

// ---------------- problem dims ----------------
#define B_ 8192
#define V_ 1024
#define E_ 640
#define H_ 640
#define L_ 2
#define D_ 512
#define J_ 640

// ---------------- GEMM tiling -----------------
#define BM 128
#define BN 128
#define BK 16
#define TM 8
#define TN 8
// 256 threads = (BM/TM) * (BN/TN) = 16 * 16

// ---------------- scratch (no allocations allowed) ----------------
__device__ float g_x[B_ * E_];            // embedded inputs (B, E)
__device__ float g_gates[B_ * 4 * H_];    // LSTM gates (B, 4H), reused per layer
__device__ float g_z[B_ * J_];            // joint hidden (B, J)

// ---------------- embedding gather ----------------
__global__ void gather_emb(const int* __restrict__ ids,
                           const float4* __restrict__ emb,
                           float4* __restrict__ x) {
    int i = blockIdx.x * blockDim.x + threadIdx.x;   // over B_*E_/4
    int b = i / (E_ / 4);
    int q = i - b * (E_ / 4);
    x[i] = emb[ids[b] * (E_ / 4) + q];
}

// ---------------- LSTM cell elementwise ----------------
__device__ __forceinline__ float sigmoidf_(float x) {
    return 1.0f / (1.0f + expf(-x));
}

__global__ void lstm_cell(const float* __restrict__ gates,
                          const float* __restrict__ c0,
                          float* __restrict__ h1,
                          float* __restrict__ c1) {
    int i = blockIdx.x * blockDim.x + threadIdx.x;   // over B_*H_
    int b = i / H_;
    int n = i - b * H_;
    const float* g = gates + (size_t)b * (4 * H_);
    float ig = sigmoidf_(g[n]);
    float fg = sigmoidf_(g[H_ + n]);
    float gg = tanhf(g[2 * H_ + n]);
    float og = sigmoidf_(g[3 * H_ + n]);
    float c  = fg * c0[i] + ig * gg;
    c1[i] = c;
    h1[i] = og * tanhf(c);
}

// ---------------- dual-operand TN GEMM ----------------
// C[M,N] = A1[M,K1] * W1[N,K1]^T + A2[M,K2] * W2[N,K2]^T + b1[N] + b2[N]
// (A2 may be nullptr -> single GEMM; b1/b2 may be nullptr)
// Requires: M % BM == 0, N % BN == 0, K % BK == 0.
__global__ void __launch_bounds__(256, 2)
gemm_dual(const float* __restrict__ A1, const float* __restrict__ W1, int K1,
          const float* __restrict__ A2, const float* __restrict__ W2, int K2,
          const float* __restrict__ b1, const float* __restrict__ b2,
          float* __restrict__ C, int N, int do_relu)
{
    __shared__ float As[BK][BM];
    __shared__ float Ws[BK][BN];

    const int tid = threadIdx.x;
    const int m0  = blockIdx.y * BM;
    const int n0  = blockIdx.x * BN;
    const int ty  = tid >> 4;     // 0..15 (M direction)
    const int tx  = tid & 15;     // 0..15 (N direction)

    float acc[TM][TN];
    #pragma unroll
    for (int i = 0; i < TM; i++)
        #pragma unroll
        for (int j = 0; j < TN; j++) acc[i][j] = 0.f;

    for (int pass = 0; pass < 2; pass++) {
        const float* A = pass ? A2 : A1;
        const float* W = pass ? W2 : W1;
        const int    K = pass ? K2 : K1;
        if (A == nullptr) continue;

        for (int k0 = 0; k0 < K; k0 += BK) {
            // Load 128x16 tiles of A and W (both K-contiguous), transpose into smem.
            #pragma unroll
            for (int j = 0; j < 2; j++) {
                int idx = tid + j * 256;           // 0..511
                int row = idx >> 2;                // 0..127
                int kq  = (idx & 3) * 4;           // 0,4,8,12
                float4 va = *reinterpret_cast<const float4*>(A + (m0 + row) * K + k0 + kq);
                As[kq + 0][row] = va.x;
                As[kq + 1][row] = va.y;
                As[kq + 2][row] = va.z;
                As[kq + 3][row] = va.w;
                float4 vw = *reinterpret_cast<const float4*>(W + (n0 + row) * K + k0 + kq);
                Ws[kq + 0][row] = vw.x;
                Ws[kq + 1][row] = vw.y;
                Ws[kq + 2][row] = vw.z;
                Ws[kq + 3][row] = vw.w;
            }
            __syncthreads();

            #pragma unroll
            for (int kk = 0; kk < BK; kk++) {
                float a[TM], w[TN];
                float4 a0 = *reinterpret_cast<const float4*>(&As[kk][ty * TM]);
                float4 a1 = *reinterpret_cast<const float4*>(&As[kk][ty * TM + 4]);
                float4 w0 = *reinterpret_cast<const float4*>(&Ws[kk][tx * TN]);
                float4 w1 = *reinterpret_cast<const float4*>(&Ws[kk][tx * TN + 4]);
                a[0] = a0.x; a[1] = a0.y; a[2] = a0.z; a[3] = a0.w;
                a[4] = a1.x; a[5] = a1.y; a[6] = a1.z; a[7] = a1.w;
                w[0] = w0.x; w[1] = w0.y; w[2] = w0.z; w[3] = w0.w;
                w[4] = w1.x; w[5] = w1.y; w[6] = w1.z; w[7] = w1.w;
                #pragma unroll
                for (int i = 0; i < TM; i++)
                    #pragma unroll
                    for (int j = 0; j < TN; j++)
                        acc[i][j] += a[i] * w[j];
            }
            __syncthreads();
        }
    }

    // Epilogue: bias (+ bias2), optional relu, vectorized stores.
    float bias[TN];
    #pragma unroll
    for (int j = 0; j < TN; j++) {
        int n = n0 + tx * TN + j;
        float bv = (b1 != nullptr) ? b1[n] : 0.f;
        if (b2 != nullptr) bv += b2[n];
        bias[j] = bv;
    }
    #pragma unroll
    for (int i = 0; i < TM; i++) {
        int m = m0 + ty * TM + i;
        float v[TN];
        #pragma unroll
        for (int j = 0; j < TN; j++) {
            float t = acc[i][j] + bias[j];
            v[j] = do_relu ? fmaxf(t, 0.f) : t;
        }
        float4* cp = reinterpret_cast<float4*>(C + (size_t)m * N + n0 + tx * TN);
        cp[0] = make_float4(v[0], v[1], v[2], v[3]);
        cp[1] = make_float4(v[4], v[5], v[6], v[7]);
    }
}

// ---------------- launch ----------------
extern "C" void kernel_launch(void* const* d_in, const int* in_sizes, int n_in,
                              void* d_out, int out_size) {
    const int*   ids    = (const int*)  d_in[0];
    const float* h0     = (const float*)d_in[1];
    const float* c0     = (const float*)d_in[2];
    const float* enc    = (const float*)d_in[3];
    const float* emb    = (const float*)d_in[4];
    const float* w_ih   = (const float*)d_in[5];
    const float* w_hh   = (const float*)d_in[6];
    const float* b_ih   = (const float*)d_in[7];
    const float* b_hh   = (const float*)d_in[8];
    const float* w_enc  = (const float*)d_in[9];
    const float* b_enc  = (const float*)d_in[10];
    const float* w_pred = (const float*)d_in[11];
    const float* b_pred = (const float*)d_in[12];
    const float* w_out  = (const float*)d_in[13];
    const float* b_out  = (const float*)d_in[14];

    float* out    = (float*)d_out;
    float* logits = out;                                 // (B, V)
    float* h1     = out + (size_t)B_ * V_;               // (L, B, H)
    float* c1     = h1  + (size_t)L_ * B_ * H_;          // (L, B, H)

    float *x, *gates, *z;
    cudaGetSymbolAddress((void**)&x,     g_x);
    cudaGetSymbolAddress((void**)&gates, g_gates);
    cudaGetSymbolAddress((void**)&z,     g_z);

    // 1) embedding gather
    gather_emb<<<(B_ * E_ / 4) / 256, 256>>>(ids, (const float4*)emb, (float4*)x);

    dim3 blk(256);
    dim3 grdG(4 * H_ / BN, B_ / BM);   // 20 x 64

    // 2) layer 0 gates: x*w_ih0^T + h0[0]*w_hh0^T + b
    gemm_dual<<<grdG, blk>>>(x, w_ih, H_,
                             h0, w_hh, H_,
                             b_ih, b_hh, gates, 4 * H_, 0);
    // 3) layer 0 cell -> h1[0], c1[0] directly in d_out
    lstm_cell<<<(B_ * H_) / 256, 256>>>(gates, c0, h1, c1);

    // 4) layer 1 gates: h1[0]*w_ih1^T + h0[1]*w_hh1^T + b
    gemm_dual<<<grdG, blk>>>(h1,          w_ih + 4 * H_ * H_, H_,
                             h0 + B_ * H_, w_hh + 4 * H_ * H_, H_,
                             b_ih + 4 * H_, b_hh + 4 * H_, gates, 4 * H_, 0);
    // 5) layer 1 cell -> h1[1] (= pred_t), c1[1]
    lstm_cell<<<(B_ * H_) / 256, 256>>>(gates, c0 + B_ * H_,
                                        h1 + B_ * H_, c1 + B_ * H_);

    // 6) joint: relu(enc*w_enc^T + pred*w_pred^T + b_enc + b_pred)
    dim3 grdJ(J_ / BN, B_ / BM);       // 5 x 64
    gemm_dual<<<grdJ, blk>>>(enc, w_enc, D_,
                             h1 + B_ * H_, w_pred, H_,
                             b_enc, b_pred, z, J_, 1);

    // 7) logits = z*w_out^T + b_out
    dim3 grdO(V_ / BN, B_ / BM);       // 8 x 64
    gemm_dual<<<grdO, blk>>>(z, w_out, J_,
                             nullptr, nullptr, 0,
                             b_out, nullptr, logits, V_, 0);
}

// round 3
// speedup vs baseline: 2.1179x; 2.1179x over previous
#include <cuda_runtime.h>
#include <cuda_bf16.h>
#include <cstdint>

// ---------------- problem dims ----------------
#define B_ 8192
#define V_ 1024
#define E_ 640
#define H_ 640
#define L_ 2
#define D_ 512
#define J_ 640

// ---------------- GEMM smem layout ----------------
#define ROWB   80                    // bytes per smem row: 32 bf16 (64B) + 16B pad
#define TILEB  (128 * ROWB)          // one 128x32 bf16 tile = 10240 B
#define STAGEB (4 * TILEB)           // Ahi, Alo, Whi, Wlo       = 40960 B
#define SMEMB  (2 * STAGEB)          // double buffered          = 81920 B

// ================= low-level helpers (base sm_100 ISA only) =================
__device__ __forceinline__ uint32_t smem_to_u32(const void* p) {
    uint32_t a;
    asm("{ .reg .u64 t; cvta.to.shared.u64 t, %1; cvt.u32.u64 %0, t; }"
        : "=r"(a) : "l"(p));
    return a;
}
__device__ __forceinline__ void cp_async16(uint32_t saddr, const void* gptr) {
    asm volatile("cp.async.cg.shared.global [%0], [%1], 16;"
                 :: "r"(saddr), "l"(gptr));
}
__device__ __forceinline__ void cp_commit() {
    asm volatile("cp.async.commit_group;");
}
template <int N>
__device__ __forceinline__ void cp_wait() {
    asm volatile("cp.async.wait_group %0;" :: "n"(N));
}
__device__ __forceinline__ void ldsm_x4(uint32_t* r, uint32_t addr) {
    asm volatile("ldmatrix.sync.aligned.m8n8.x4.shared.b16 {%0,%1,%2,%3}, [%4];"
                 : "=r"(r[0]), "=r"(r[1]), "=r"(r[2]), "=r"(r[3]) : "r"(addr));
}
__device__ __forceinline__ void mma_bf16(float* c, const uint32_t* a,
                                         uint32_t b0, uint32_t b1) {
    asm volatile(
        "mma.sync.aligned.m16n8k16.row.col.f32.bf16.bf16.f32 "
        "{%0,%1,%2,%3}, {%4,%5,%6,%7}, {%8,%9}, {%0,%1,%2,%3};"
        : "+f"(c[0]), "+f"(c[1]), "+f"(c[2]), "+f"(c[3])
        : "r"(a[0]), "r"(a[1]), "r"(a[2]), "r"(a[3]), "r"(b0), "r"(b1));
}

// ================= scratch (no allocations allowed) =================
__device__ float g_gates[B_ * 4 * H_];
__device__ __align__(16) __nv_bfloat16 g_xhi[B_ * E_],  g_xlo[B_ * E_];
__device__ __align__(16) __nv_bfloat16 g_h0hi[L_ * B_ * H_], g_h0lo[L_ * B_ * H_];
__device__ __align__(16) __nv_bfloat16 g_h1hi[L_ * B_ * H_], g_h1lo[L_ * B_ * H_];
__device__ __align__(16) __nv_bfloat16 g_enchi[B_ * D_], g_enclo[B_ * D_];
__device__ __align__(16) __nv_bfloat16 g_zhi[B_ * J_],  g_zlo[B_ * J_];
__device__ __align__(16) __nv_bfloat16 g_wihhi[L_ * 4 * H_ * H_], g_wihlo[L_ * 4 * H_ * H_];
__device__ __align__(16) __nv_bfloat16 g_whhhi[L_ * 4 * H_ * H_], g_whhlo[L_ * 4 * H_ * H_];
__device__ __align__(16) __nv_bfloat16 g_wenchi[J_ * D_], g_wenclo[J_ * D_];
__device__ __align__(16) __nv_bfloat16 g_wpredhi[J_ * H_], g_wpredlo[J_ * H_];
__device__ __align__(16) __nv_bfloat16 g_wouthi[V_ * J_], g_woutlo[V_ * J_];

// ================= elementwise kernels =================
__device__ __forceinline__ void split1(float v, __nv_bfloat16& h, __nv_bfloat16& l) {
    h = __float2bfloat16_rn(v);
    l = __float2bfloat16_rn(v - __bfloat162float(h));
}

__global__ void split_bf16(const float4* __restrict__ in,
                           __nv_bfloat162* __restrict__ hi,
                           __nv_bfloat162* __restrict__ lo, int n4) {
    int i = blockIdx.x * blockDim.x + threadIdx.x;
    if (i >= n4) return;
    float4 v = in[i];
    __nv_bfloat16 hx, lx, hy, ly, hz, lz, hw, lw;
    split1(v.x, hx, lx); split1(v.y, hy, ly);
    split1(v.z, hz, lz); split1(v.w, hw, lw);
    __nv_bfloat162 t;
    t.x = hx; t.y = hy; hi[2 * i]     = t;
    t.x = hz; t.y = hw; hi[2 * i + 1] = t;
    t.x = lx; t.y = ly; lo[2 * i]     = t;
    t.x = lz; t.y = lw; lo[2 * i + 1] = t;
}

__global__ void gather_split(const int* __restrict__ ids,
                             const float4* __restrict__ emb,
                             __nv_bfloat162* __restrict__ xhi,
                             __nv_bfloat162* __restrict__ xlo) {
    int i = blockIdx.x * blockDim.x + threadIdx.x;   // over B_*(E_/4)
    if (i >= B_ * (E_ / 4)) return;
    int b = i / (E_ / 4);
    int q = i - b * (E_ / 4);
    float4 v = emb[(size_t)ids[b] * (E_ / 4) + q];
    __nv_bfloat16 hx, lx, hy, ly, hz, lz, hw, lw;
    split1(v.x, hx, lx); split1(v.y, hy, ly);
    split1(v.z, hz, lz); split1(v.w, hw, lw);
    size_t o = (size_t)b * (E_ / 2) + q * 2;
    __nv_bfloat162 t;
    t.x = hx; t.y = hy; xhi[o]     = t;
    t.x = hz; t.y = hw; xhi[o + 1] = t;
    t.x = lx; t.y = ly; xlo[o]     = t;
    t.x = lz; t.y = lw; xlo[o + 1] = t;
}

__device__ __forceinline__ float sigmoidf_(float x) {
    return 1.0f / (1.0f + expf(-x));
}

__global__ void lstm_cell(const float* __restrict__ gates,
                          const float* __restrict__ c0,
                          float* __restrict__ h1f, float* __restrict__ c1f,
                          __nv_bfloat16* __restrict__ h1hi,
                          __nv_bfloat16* __restrict__ h1lo) {
    int i = blockIdx.x * blockDim.x + threadIdx.x;   // over B_*H_
    if (i >= B_ * H_) return;
    int b = i / H_;
    int n = i - b * H_;
    const float* g = gates + (size_t)b * (4 * H_);
    float ig = sigmoidf_(g[n]);
    float fg = sigmoidf_(g[H_ + n]);
    float gg = tanhf(g[2 * H_ + n]);
    float og = sigmoidf_(g[3 * H_ + n]);
    float c  = fg * c0[i] + ig * gg;
    float h  = og * tanhf(c);
    c1f[i] = c;
    h1f[i] = h;
    __nv_bfloat16 hh, hl;
    split1(h, hh, hl);
    h1hi[i] = hh;
    h1lo[i] = hl;
}

// ================= split-bf16 HMMA GEMM =================
// C[M,N] = A1*W1^T + A2*W2^T (+b1(+b2), opt relu), 2-way bf16 split:
//   hi*hi + hi*lo + lo*hi per operand pair.
// CTA tile 128x128, K chunks of 32, warp tile 64x32 (8 warps = 2x4).
// If Chi != nullptr: write hi/lo bf16 split of C; else fp32 to Cf.
__global__ void __launch_bounds__(256, 1)
gemm_hmma(const __nv_bfloat16* __restrict__ A1h, const __nv_bfloat16* __restrict__ A1l,
          const __nv_bfloat16* __restrict__ W1h, const __nv_bfloat16* __restrict__ W1l, int K1,
          const __nv_bfloat16* __restrict__ A2h, const __nv_bfloat16* __restrict__ A2l,
          const __nv_bfloat16* __restrict__ W2h, const __nv_bfloat16* __restrict__ W2l, int K2,
          const float* __restrict__ b1, const float* __restrict__ b2,
          float* __restrict__ Cf,
          __nv_bfloat16* __restrict__ Chi, __nv_bfloat16* __restrict__ Clo,
          int ldc, int relu)
{
    extern __shared__ char smem[];
    const uint32_t sbase = smem_to_u32(smem);
    const int tid = threadIdx.x;
    const int wid = tid >> 5;
    const int lid = tid & 31;
    const int m0  = blockIdx.y * 128;
    const int n0  = blockIdx.x * 128;
    const int wm  = (wid & 1) * 64;     // warp M offset in tile
    const int wn  = (wid >> 1) * 32;    // warp N offset in tile

    float acc[4][4][4];
    #pragma unroll
    for (int i = 0; i < 4; i++)
        #pragma unroll
        for (int j = 0; j < 4; j++)
            #pragma unroll
            for (int k = 0; k < 4; k++) acc[i][j][k] = 0.f;

    const int nch1 = K1 / 32;
    const int nch  = nch1 + K2 / 32;

    // per-thread load coords: 2 rows per tile, 4 tiles
    const int lrow = tid >> 2;          // 0..63
    const int lcg  = tid & 3;           // 16B column group

    auto load_chunk = [&](int c) {
        const __nv_bfloat16 *pAh, *pAl, *pWh, *pWl;
        int kbase, Kc;
        if (c < nch1) { pAh = A1h; pAl = A1l; pWh = W1h; pWl = W1l; kbase = c * 32; Kc = K1; }
        else          { pAh = A2h; pAl = A2l; pWh = W2h; pWl = W2l; kbase = (c - nch1) * 32; Kc = K2; }
        const uint32_t st = sbase + (uint32_t)(c & 1) * STAGEB;
        #pragma unroll
        for (int m = 0; m < 4; ++m) {
            const __nv_bfloat16* src = (m == 0) ? pAh : (m == 1) ? pAl : (m == 2) ? pWh : pWl;
            const int rb = (m < 2) ? m0 : n0;
            #pragma unroll
            for (int pp = 0; pp < 2; ++pp) {
                int r = lrow + pp * 64;
                const void* g = src + (size_t)(rb + r) * Kc + kbase + lcg * 8;
                uint32_t s = st + m * TILEB + r * ROWB + lcg * 16;
                cp_async16(s, g);
            }
        }
        cp_commit();
    };

    load_chunk(0);

    for (int c = 0; c < nch; ++c) {
        if (c + 1 < nch) {
            load_chunk(c + 1);
            cp_wait<1>();
        } else {
            cp_wait<0>();
        }
        __syncthreads();

        const uint32_t st = sbase + (uint32_t)(c & 1) * STAGEB;
        #pragma unroll
        for (int ks = 0; ks < 2; ++ks) {
            const int kb = ks * 32;     // byte offset of 16-elem k-step
            uint32_t ah[4][4], al[4][4];
            #pragma unroll
            for (int mf = 0; mf < 4; ++mf) {
                uint32_t addr = st + (wm + mf * 16 + (lid & 15)) * ROWB
                              + kb + ((lid >> 4) * 16);
                ldsm_x4(ah[mf], addr);
                ldsm_x4(al[mf], addr + TILEB);
            }
            uint32_t bh[2][4], bl[2][4];
            #pragma unroll
            for (int ng = 0; ng < 2; ++ng) {
                int nrow = wn + ng * 16 + ((lid >> 4) << 3) + (lid & 7);
                int kof  = ((lid >> 3) & 1) * 16;
                uint32_t addr = st + 2 * TILEB + nrow * ROWB + kb + kof;
                ldsm_x4(bh[ng], addr);
                ldsm_x4(bl[ng], addr + TILEB);
            }
            #pragma unroll
            for (int mf = 0; mf < 4; ++mf)
                #pragma unroll
                for (int nf = 0; nf < 4; ++nf) {
                    const int ng = nf >> 1, hf = (nf & 1) * 2;
                    mma_bf16(acc[mf][nf], ah[mf], bh[ng][hf], bh[ng][hf + 1]);
                    mma_bf16(acc[mf][nf], ah[mf], bl[ng][hf], bl[ng][hf + 1]);
                    mma_bf16(acc[mf][nf], al[mf], bh[ng][hf], bh[ng][hf + 1]);
                }
        }
        __syncthreads();
    }

    // ---- epilogue ----
    const int g = lid >> 2;
    const int t = lid & 3;
    #pragma unroll
    for (int nf = 0; nf < 4; ++nf) {
        const int col = n0 + wn + nf * 8 + t * 2;
        float bb0 = b1[col],     bb1 = b1[col + 1];
        if (b2) { bb0 += b2[col]; bb1 += b2[col + 1]; }
        #pragma unroll
        for (int mf = 0; mf < 4; ++mf) {
            const int r0 = m0 + wm + mf * 16 + g;
            const int r1 = r0 + 8;
            float v00 = acc[mf][nf][0] + bb0;
            float v01 = acc[mf][nf][1] + bb1;
            float v10 = acc[mf][nf][2] + bb0;
            float v11 = acc[mf][nf][3] + bb1;
            if (relu) {
                v00 = fmaxf(v00, 0.f); v01 = fmaxf(v01, 0.f);
                v10 = fmaxf(v10, 0.f); v11 = fmaxf(v11, 0.f);
            }
            if (Chi) {
                __nv_bfloat16 h0b, l0b, h1b, l1b;
                __nv_bfloat162 th, tl;
                split1(v00, h0b, l0b); split1(v01, h1b, l1b);
                th.x = h0b; th.y = h1b; tl.x = l0b; tl.y = l1b;
                *reinterpret_cast<__nv_bfloat162*>(Chi + (size_t)r0 * ldc + col) = th;
                *reinterpret_cast<__nv_bfloat162*>(Clo + (size_t)r0 * ldc + col) = tl;
                split1(v10, h0b, l0b); split1(v11, h1b, l1b);
                th.x = h0b; th.y = h1b; tl.x = l0b; tl.y = l1b;
                *reinterpret_cast<__nv_bfloat162*>(Chi + (size_t)r1 * ldc + col) = th;
                *reinterpret_cast<__nv_bfloat162*>(Clo + (size_t)r1 * ldc + col) = tl;
            } else {
                *reinterpret_cast<float2*>(Cf + (size_t)r0 * ldc + col) = make_float2(v00, v01);
                *reinterpret_cast<float2*>(Cf + (size_t)r1 * ldc + col) = make_float2(v10, v11);
            }
        }
    }
}

// ================= launch =================
extern "C" void kernel_launch(void* const* d_in, const int* in_sizes, int n_in,
                              void* d_out, int out_size) {
    const int*   ids    = (const int*)  d_in[0];
    const float* h0     = (const float*)d_in[1];
    const float* c0     = (const float*)d_in[2];
    const float* enc    = (const float*)d_in[3];
    const float* emb    = (const float*)d_in[4];
    const float* w_ih   = (const float*)d_in[5];
    const float* w_hh   = (const float*)d_in[6];
    const float* b_ih   = (const float*)d_in[7];
    const float* b_hh   = (const float*)d_in[8];
    const float* w_enc  = (const float*)d_in[9];
    const float* b_enc  = (const float*)d_in[10];
    const float* w_pred = (const float*)d_in[11];
    const float* b_pred = (const float*)d_in[12];
    const float* w_out  = (const float*)d_in[13];
    const float* b_out  = (const float*)d_in[14];

    float* out    = (float*)d_out;
    float* logits = out;                                 // (B, V)
    float* h1f    = out + (size_t)B_ * V_;               // (L, B, H)
    float* c1f    = h1f + (size_t)L_ * B_ * H_;          // (L, B, H)

    float* gates;
    __nv_bfloat16 *xhi, *xlo, *h0hi, *h0lo, *h1hi, *h1lo, *enchi, *enclo, *zhi, *zlo;
    __nv_bfloat16 *wihhi, *wihlo, *whhhi, *whhlo, *wenchi, *wenclo,
                  *wpredhi, *wpredlo, *wouthi, *woutlo;
    cudaGetSymbolAddress((void**)&gates, g_gates);
    cudaGetSymbolAddress((void**)&xhi, g_xhi);       cudaGetSymbolAddress((void**)&xlo, g_xlo);
    cudaGetSymbolAddress((void**)&h0hi, g_h0hi);     cudaGetSymbolAddress((void**)&h0lo, g_h0lo);
    cudaGetSymbolAddress((void**)&h1hi, g_h1hi);     cudaGetSymbolAddress((void**)&h1lo, g_h1lo);
    cudaGetSymbolAddress((void**)&enchi, g_enchi);   cudaGetSymbolAddress((void**)&enclo, g_enclo);
    cudaGetSymbolAddress((void**)&zhi, g_zhi);       cudaGetSymbolAddress((void**)&zlo, g_zlo);
    cudaGetSymbolAddress((void**)&wihhi, g_wihhi);   cudaGetSymbolAddress((void**)&wihlo, g_wihlo);
    cudaGetSymbolAddress((void**)&whhhi, g_whhhi);   cudaGetSymbolAddress((void**)&whhlo, g_whhlo);
    cudaGetSymbolAddress((void**)&wenchi, g_wenchi); cudaGetSymbolAddress((void**)&wenclo, g_wenclo);
    cudaGetSymbolAddress((void**)&wpredhi, g_wpredhi); cudaGetSymbolAddress((void**)&wpredlo, g_wpredlo);
    cudaGetSymbolAddress((void**)&wouthi, g_wouthi); cudaGetSymbolAddress((void**)&woutlo, g_woutlo);

    cudaFuncSetAttribute(gemm_hmma, cudaFuncAttributeMaxDynamicSharedMemorySize, SMEMB);

    const int T = 256;
    auto grid1d = [](long n) { return (int)((n + 255) / 256); };

    // ---- splits ----
    gather_split<<<grid1d(B_ * (E_ / 4)), T>>>(ids, (const float4*)emb,
                                               (__nv_bfloat162*)xhi, (__nv_bfloat162*)xlo);
    split_bf16<<<grid1d((long)L_ * B_ * H_ / 4), T>>>((const float4*)h0,
        (__nv_bfloat162*)h0hi, (__nv_bfloat162*)h0lo, L_ * B_ * H_ / 4);
    split_bf16<<<grid1d((long)B_ * D_ / 4), T>>>((const float4*)enc,
        (__nv_bfloat162*)enchi, (__nv_bfloat162*)enclo, B_ * D_ / 4);
    split_bf16<<<grid1d((long)L_ * 4 * H_ * H_ / 4), T>>>((const float4*)w_ih,
        (__nv_bfloat162*)wihhi, (__nv_bfloat162*)wihlo, L_ * 4 * H_ * H_ / 4);
    split_bf16<<<grid1d((long)L_ * 4 * H_ * H_ / 4), T>>>((const float4*)w_hh,
        (__nv_bfloat162*)whhhi, (__nv_bfloat162*)whhlo, L_ * 4 * H_ * H_ / 4);
    split_bf16<<<grid1d((long)J_ * D_ / 4), T>>>((const float4*)w_enc,
        (__nv_bfloat162*)wenchi, (__nv_bfloat162*)wenclo, J_ * D_ / 4);
    split_bf16<<<grid1d((long)J_ * H_ / 4), T>>>((const float4*)w_pred,
        (__nv_bfloat162*)wpredhi, (__nv_bfloat162*)wpredlo, J_ * H_ / 4);
    split_bf16<<<grid1d((long)V_ * J_ / 4), T>>>((const float4*)w_out,
        (__nv_bfloat162*)wouthi, (__nv_bfloat162*)woutlo, V_ * J_ / 4);

    const int WIH = 4 * H_ * H_;     // per-layer w_ih/w_hh elems
    const int BH  = B_ * H_;         // per-layer h slice elems

    dim3 blk(256);
    dim3 grdG(4 * H_ / 128, B_ / 128);   // 20 x 64

    // ---- layer 0 gates ----
    gemm_hmma<<<grdG, blk, SMEMB>>>(
        xhi, xlo, wihhi, wihlo, H_,
        h0hi, h0lo, whhhi, whhlo, H_,
        b_ih, b_hh, gates, nullptr, nullptr, 4 * H_, 0);
    lstm_cell<<<grid1d((long)BH), T>>>(gates, c0, h1f, c1f, h1hi, h1lo);

    // ---- layer 1 gates ----
    gemm_hmma<<<grdG, blk, SMEMB>>>(
        h1hi, h1lo, wihhi + WIH, wihlo + WIH, H_,
        h0hi + BH, h0lo + BH, whhhi + WIH, whhlo + WIH, H_,
        b_ih + 4 * H_, b_hh + 4 * H_, gates, nullptr, nullptr, 4 * H_, 0);
    lstm_cell<<<grid1d((long)BH), T>>>(gates, c0 + BH, h1f + BH, c1f + BH,
                                       h1hi + BH, h1lo + BH);

    // ---- joint: relu(enc*w_enc^T + pred*w_pred^T + b) -> split z ----
    dim3 grdJ(J_ / 128, B_ / 128);       // 5 x 64
    gemm_hmma<<<grdJ, blk, SMEMB>>>(
        enchi, enclo, wenchi, wenclo, D_,
        h1hi + BH, h1lo + BH, wpredhi, wpredlo, H_,
        b_enc, b_pred, nullptr, zhi, zlo, J_, 1);

    // ---- logits = z*w_out^T + b_out ----
    dim3 grdO(V_ / 128, B_ / 128);       // 8 x 64
    gemm_hmma<<<grdO, blk, SMEMB>>>(
        zhi, zlo, wouthi, woutlo, J_,
        nullptr, nullptr, nullptr, nullptr, 0,
        b_out, nullptr, logits, nullptr, nullptr, V_, 0);
}